// round 13
// baseline (speedup 1.0000x reference)
#include <cuda_runtime.h>
#include <stdint.h>

#define NPTS    262144
#define NWTILES 8192          // warp-tiles of 32 points
#define TMASK   0x7FFFFu
#define RS      104           // staging row stride: work cols 0..63, X cols 64..95
#define THREADS 384
#define NWARP   12
#define NCTA    148
#define STRIDE  (NCTA * NWARP)   // 1776 warp-streams

// weight fragment arrays (uint4 units)
#define WF_L1 0               // Kt2 Nt8 -> 512
#define WF_L2 512             // Kt4 Nt2 -> 256
#define WF_C1 768             // Kt2 Nt8 -> 512
#define WF_C2 1280            // Kt4 Nt8 -> 1024
#define WF_C3 2304            // Kt4 Nt8 -> 1024
#define WF_C4 3328            // Kt4 Nt1 -> 128
#define WF_TOT 3456
#define BIAS_F (WF_TOT * 4)   // float idx 13824
#define STG_F  (BIAS_F + 280) // 14104, 16B aligned
#define SMEM_FLOATS (STG_F + NWARP * 32 * RS)
#define SMEM_BYTES  (SMEM_FLOATS * 4)   // 216,160 B

typedef unsigned long long u64;

__constant__ float RESV[16] = {16.f, 20.f, 25.f, 32.f, 40.f, 50.f, 64.f, 80.f,
                               101.f, 128.f, 161.f, 203.f, 256.f, 322.f, 406.f, 512.f};

__device__ __forceinline__ uint32_t pkb(float lo, float hi) {
    uint32_t r; asm("cvt.rn.bf16x2.f32 %0, %1, %2;" : "=r"(r) : "f"(hi), "f"(lo)); return r;
}
__device__ __forceinline__ float lof(uint32_t u) { return __uint_as_float(u << 16); }
__device__ __forceinline__ float hif(uint32_t u) { return __uint_as_float(u & 0xffff0000u); }

__device__ __forceinline__ void mma16(float* d, const uint32_t* a, uint32_t b0, uint32_t b1) {
    asm volatile(
        "mma.sync.aligned.m16n8k16.row.col.f32.bf16.bf16.f32 "
        "{%0,%1,%2,%3},{%4,%5,%6,%7},{%8,%9},{%0,%1,%2,%3};"
        : "+f"(d[0]), "+f"(d[1]), "+f"(d[2]), "+f"(d[3])
        : "r"(a[0]), "r"(a[1]), "r"(a[2]), "r"(a[3]), "r"(b0), "r"(b1));
}

// acc[Nt][4] = A(16xK fp32 staging @ col inoff) @ W(KxN), 3-pass bf16
template<int K, int N>
__device__ __forceinline__ void mma_compute(const uint4* __restrict__ Wf,
                                            const float* __restrict__ Aw,
                                            int m, int lane, int inoff,
                                            float acc[N / 8][4])
{
    constexpr int Kt = K / 16, Nt = N / 8;
    const int g = lane >> 2, tig = lane & 3;
#pragma unroll
    for (int nt = 0; nt < Nt; nt++)
        acc[nt][0] = acc[nt][1] = acc[nt][2] = acc[nt][3] = 0.f;
    const float* base = Aw + (16 * m + g) * RS + 2 * tig + inoff;
#pragma unroll
    for (int kt = 0; kt < Kt; kt++) {
        const float* ar = base + kt * 16;
        float2 va = *(const float2*)(ar);
        float2 vc = *(const float2*)(ar + 8 * RS);
        float2 vb = *(const float2*)(ar + 8);
        float2 vd = *(const float2*)(ar + 8 * RS + 8);
        uint32_t ah[4], al[4];
        ah[0] = pkb(va.x, va.y); al[0] = pkb(va.x - lof(ah[0]), va.y - hif(ah[0]));
        ah[1] = pkb(vc.x, vc.y); al[1] = pkb(vc.x - lof(ah[1]), vc.y - hif(ah[1]));
        ah[2] = pkb(vb.x, vb.y); al[2] = pkb(vb.x - lof(ah[2]), vb.y - hif(ah[2]));
        ah[3] = pkb(vd.x, vd.y); al[3] = pkb(vd.x - lof(ah[3]), vd.y - hif(ah[3]));
#pragma unroll
        for (int nt = 0; nt < Nt; nt++) {
            uint4 B = Wf[(nt * Kt + kt) * 32 + lane];
            mma16(acc[nt], ah, B.x, B.y);
            mma16(acc[nt], al, B.x, B.y);
            mma16(acc[nt], ah, B.z, B.w);
        }
    }
}

// relu layer with per-m-tile hook (for gather pipelining)
template<int K, int N, class F>
__device__ __forceinline__ void layer_relu(const uint4* __restrict__ Wf,
                                           const float* __restrict__ bias,
                                           float* __restrict__ Aw, int lane,
                                           int inoff, F&& hook)
{
    constexpr int Nt = N / 8;
    const int g = lane >> 2, tig = lane & 3;
#pragma unroll
    for (int m = 0; m < 2; m++) {
        float acc[Nt][4];
        mma_compute<K, N>(Wf, Aw, m, lane, inoff, acc);
        __syncwarp();
        float* s0 = Aw + (16 * m + g) * RS + 2 * tig;
#pragma unroll
        for (int nt = 0; nt < Nt; nt++) {
            float b0 = bias[nt * 8 + 2 * tig], b1 = bias[nt * 8 + 2 * tig + 1];
            *(float2*)(s0 + nt * 8) =
                make_float2(fmaxf(acc[nt][0] + b0, 0.f), fmaxf(acc[nt][1] + b1, 0.f));
            *(float2*)(s0 + 8 * RS + nt * 8) =
                make_float2(fmaxf(acc[nt][2] + b0, 0.f), fmaxf(acc[nt][3] + b1, 0.f));
        }
        hook(m);
    }
    __syncwarp();
}

// density layer 2: 64 -> 16, no relu, writes dout to X cols 80..95
__device__ __forceinline__ void layer_l2(const uint4* __restrict__ Wf,
                                         const float* __restrict__ bias,
                                         float* __restrict__ Aw, int lane)
{
    const int g = lane >> 2, tig = lane & 3;
#pragma unroll
    for (int m = 0; m < 2; m++) {
        float acc[2][4];
        mma_compute<64, 16>(Wf, Aw, m, lane, 0, acc);
        __syncwarp();
        float* s0 = Aw + (16 * m + g) * RS + 80 + 2 * tig;
#pragma unroll
        for (int nt = 0; nt < 2; nt++) {
            float b0 = bias[nt * 8 + 2 * tig], b1 = bias[nt * 8 + 2 * tig + 1];
            *(float2*)(s0 + nt * 8) = make_float2(acc[nt][0] + b0, acc[nt][1] + b1);
            *(float2*)(s0 + 8 * RS + nt * 8) = make_float2(acc[nt][2] + b0, acc[nt][3] + b1);
        }
    }
    __syncwarp();
}

__device__ __forceinline__ float sigm(float v) { return 1.f / (1.f + expf(-v)); }

template<class F>
__device__ __forceinline__ void layer_c4(const uint4* __restrict__ Wf,
                                         const float* __restrict__ bias,
                                         const float* __restrict__ Aw, int lane,
                                         float* __restrict__ out, int pbase, F&& hook)
{
    const int g = lane >> 2, tig = lane & 3;
#pragma unroll
    for (int m = 0; m < 2; m++) {
        float acc[1][4];
        mma_compute<64, 8>(Wf, Aw, m, lane, 0, acc);
        int r0 = pbase + 16 * m + g;
        int c = 2 * tig;
        if (c < 3) {
            float b = bias[c];
            out[NPTS + 3 * r0 + c]       = sigm(acc[0][0] + b);
            out[NPTS + 3 * (r0 + 8) + c] = sigm(acc[0][2] + b);
        }
        if (c + 1 < 3) {
            float b = bias[c + 1];
            out[NPTS + 3 * r0 + c + 1]       = sigm(acc[0][1] + b);
            out[NPTS + 3 * (r0 + 8) + c + 1] = sigm(acc[0][3] + b);
        }
        hook(m);
    }
    __syncwarp();
}

__device__ __forceinline__ void stage_w(uint4* __restrict__ dst, const float* __restrict__ w,
                                        int Kt, int Nt, int rN, int tid)
{
    int tot = Kt * Nt * 32;
    for (int idx = tid; idx < tot; idx += THREADS) {
        int lane = idx & 31, f = idx >> 5;
        int kt = f % Kt, nt = f / Kt;
        int g = lane >> 2, tig = lane & 3;
        int n = nt * 8 + g;
        int k0 = kt * 16 + 2 * tig;
        float w00 = 0.f, w01 = 0.f, w10 = 0.f, w11 = 0.f;
        if (n < rN) {
            w00 = w[k0 * rN + n];       w01 = w[(k0 + 1) * rN + n];
            w10 = w[(k0 + 8) * rN + n]; w11 = w[(k0 + 9) * rN + n];
        }
        uint32_t h0 = pkb(w00, w01), h1 = pkb(w10, w11);
        uint32_t l0 = pkb(w00 - lof(h0), w01 - hif(h0));
        uint32_t l1 = pkb(w10 - lof(h1), w11 - hif(h1));
        dst[idx] = make_uint4(h0, h1, l0, l1);
    }
}

// issue the 16 gathers of a 2-level group k (levels 2k, 2k+1)
__device__ __forceinline__ void issue2(const u64* __restrict__ emb, int k,
                                       float cx, float cy, float cz, u64* eb)
{
#pragma unroll
    for (int j = 0; j < 2; j++) {
        const int l = 2 * k + j;
        const float r = RESV[l];
        uint32_t px = (uint32_t)floorf(cx * r);
        uint32_t py = (uint32_t)floorf(cy * r);
        uint32_t pz = (uint32_t)floorf(cz * r);
        uint32_t hx0 = px,                hx1 = px + 1u;
        uint32_t hy0 = py * 2654435761u,  hy1 = hy0 + 2654435761u;
        uint32_t hz0 = pz * 805459861u,   hz1 = hz0 + 805459861u;
        const u64* tt = emb + ((size_t)l << 19);
        eb[8 * j + 0] = __ldg(tt + ((hx0 ^ hy0 ^ hz0) & TMASK));
        eb[8 * j + 1] = __ldg(tt + ((hx0 ^ hy0 ^ hz1) & TMASK));
        eb[8 * j + 2] = __ldg(tt + ((hx0 ^ hy1 ^ hz0) & TMASK));
        eb[8 * j + 3] = __ldg(tt + ((hx0 ^ hy1 ^ hz1) & TMASK));
        eb[8 * j + 4] = __ldg(tt + ((hx1 ^ hy0 ^ hz0) & TMASK));
        eb[8 * j + 5] = __ldg(tt + ((hx1 ^ hy0 ^ hz1) & TMASK));
        eb[8 * j + 6] = __ldg(tt + ((hx1 ^ hy1 ^ hz0) & TMASK));
        eb[8 * j + 7] = __ldg(tt + ((hx1 ^ hy1 ^ hz1) & TMASK));
    }
}

// interpolate group k and write feat cols 64+4k .. 67+4k of frow
__device__ __forceinline__ void consume2(int k, const u64* eb,
                                         float cx, float cy, float cz,
                                         float* __restrict__ frow)
{
    float o[4];
#pragma unroll
    for (int j = 0; j < 2; j++) {
        const int l = 2 * k + j;
        const float r = RESV[l];
        float fx = cx * r, fy = cy * r, fz = cz * r;
        float tx = fx - floorf(fx), ty = fy - floorf(fy), tz = fz - floorf(fz);
        float ux = 1.f - tx, uy = 1.f - ty, uz = 1.f - tz;
        float w00 = ux * uy, w01 = ux * ty, w10 = tx * uy, w11 = tx * ty;
        float2 v; float a0 = 0.f, a1 = 0.f, w;
        w = w00 * uz; v = *(float2*)&eb[8 * j + 0]; a0 = fmaf(w, v.x, a0); a1 = fmaf(w, v.y, a1);
        w = w00 * tz; v = *(float2*)&eb[8 * j + 1]; a0 = fmaf(w, v.x, a0); a1 = fmaf(w, v.y, a1);
        w = w01 * uz; v = *(float2*)&eb[8 * j + 2]; a0 = fmaf(w, v.x, a0); a1 = fmaf(w, v.y, a1);
        w = w01 * tz; v = *(float2*)&eb[8 * j + 3]; a0 = fmaf(w, v.x, a0); a1 = fmaf(w, v.y, a1);
        w = w10 * uz; v = *(float2*)&eb[8 * j + 4]; a0 = fmaf(w, v.x, a0); a1 = fmaf(w, v.y, a1);
        w = w10 * tz; v = *(float2*)&eb[8 * j + 5]; a0 = fmaf(w, v.x, a0); a1 = fmaf(w, v.y, a1);
        w = w11 * uz; v = *(float2*)&eb[8 * j + 6]; a0 = fmaf(w, v.x, a0); a1 = fmaf(w, v.y, a1);
        w = w11 * tz; v = *(float2*)&eb[8 * j + 7]; a0 = fmaf(w, v.x, a0); a1 = fmaf(w, v.y, a1);
        o[2 * j] = a0; o[2 * j + 1] = a1;
    }
    *(float4*)(frow + 64 + 4 * k) = make_float4(o[0], o[1], o[2], o[3]);
}

// blocking hash for the first tile of each warp-stream (fills X cols 64..95)
__device__ __forceinline__ void hash_blocking(const u64* __restrict__ emb,
                                              float cx, float cy, float cz,
                                              float* __restrict__ frow)
{
#pragma unroll
    for (int k = 0; k < 8; k++) {
        u64 eb[16];
        issue2(emb, k, cx, cy, cz, eb);
        consume2(k, eb, cx, cy, cz, frow);
    }
}

__global__ void __launch_bounds__(THREADS, 1)
nerf_mma_kernel(const float* __restrict__ coords,
                const float* __restrict__ dirs,
                const u64*   __restrict__ emb,
                const float* __restrict__ dw1, const float* __restrict__ db1,
                const float* __restrict__ dw2, const float* __restrict__ db2,
                const float* __restrict__ cw1, const float* __restrict__ cb1,
                const float* __restrict__ cw2, const float* __restrict__ cb2,
                const float* __restrict__ cw3, const float* __restrict__ cb3,
                const float* __restrict__ cw4, const float* __restrict__ cb4,
                float* __restrict__ out)
{
    extern __shared__ float sm[];
    uint4* wf = (uint4*)sm;
    const int tid = threadIdx.x;

    stage_w(wf + WF_L1, dw1, 2, 8, 64, tid);
    stage_w(wf + WF_L2, dw2, 4, 2, 16, tid);
    stage_w(wf + WF_C1, cw1, 2, 8, 64, tid);
    stage_w(wf + WF_C2, cw2, 4, 8, 64, tid);
    stage_w(wf + WF_C3, cw3, 4, 8, 64, tid);
    stage_w(wf + WF_C4, cw4, 4, 1,  3, tid);
    for (int i = tid; i < 64; i += THREADS) sm[BIAS_F + i] = db1[i];
    for (int i = tid; i < 16; i += THREADS) sm[BIAS_F + 64 + i] = db2[i];
    for (int i = tid; i < 64; i += THREADS) sm[BIAS_F + 80 + i] = cb1[i];
    for (int i = tid; i < 64; i += THREADS) sm[BIAS_F + 144 + i] = cb2[i];
    for (int i = tid; i < 64; i += THREADS) sm[BIAS_F + 208 + i] = cb3[i];
    for (int i = tid; i < 8;  i += THREADS) sm[BIAS_F + 272 + i] = (i < 3) ? cb4[i] : 0.f;
    __syncthreads();

    const int lane = tid & 31, warp = tid >> 5;
    float* Aw = sm + STG_F + warp * (32 * RS);
    float* frow = Aw + lane * RS;
    const float* bias = sm + BIAS_F;

    auto nohook = [](int) {};

    bool first = true;
    for (int wt = blockIdx.x * NWARP + warp; wt < NWTILES; wt += STRIDE) {
        const int p = wt * 32 + lane;

        // next-tile info for the gather pipeline
        const int wtn = wt + STRIDE;
        const bool have_next = (wtn < NWTILES);
        float cxn = 0.f, cyn = 0.f, czn = 0.f;
        if (have_next) {
            const int pn = wtn * 32 + lane;
            cxn = coords[3 * pn + 0];
            cyn = coords[3 * pn + 1];
            czn = coords[3 * pn + 2];
        }

        if (first) {
            // prologue: blocking hash fills X for this stream's first tile
            const float cx = coords[3 * p + 0];
            const float cy = coords[3 * p + 1];
            const float cz = coords[3 * p + 2];
            hash_blocking(emb, cx, cy, cz, frow);
            first = false;
            __syncwarp();
        }

        float dxr = dirs[3 * p + 0];
        float dyr = dirs[3 * p + 1];
        float dzr = dirs[3 * p + 2];

        // ---------- density MLP: D-L1 reads feats from X (inoff=64) ----------
        layer_relu<32, 64>(wf + WF_L1, bias, Aw, lane, 64, nohook);
        layer_l2(wf + WF_L2, bias + 64, Aw, lane);   // dout -> X cols 80..95

        out[p] = expf(frow[80]);

        // ---------- SH deg-4 into X cols 64..79 ----------
        {
            float nrm = sqrtf(dxr * dxr + dyr * dyr + dzr * dzr);
            float x = dxr / nrm, y = dyr / nrm, z = dzr / nrm;
            x = ((x + 1.f) * 0.5f) * 2.f - 1.f;
            y = ((y + 1.f) * 0.5f) * 2.f - 1.f;
            z = ((z + 1.f) * 0.5f) * 2.f - 1.f;
            float xx = x * x, yy = y * y, zz = z * z;
            float xy = x * y, yz = y * z, xz = x * z;
            *(float4*)(frow + 64) = make_float4(
                0.28209479177387814f,
                -0.48860251190291987f * y,
                 0.48860251190291987f * z,
                -0.48860251190291987f * x);
            *(float4*)(frow + 68) = make_float4(
                 1.0925484305920792f * xy,
                -1.0925484305920792f * yz,
                 0.94617469575756f * zz - 0.31539156525252f,
                -1.0925484305920792f * xz);
            *(float4*)(frow + 72) = make_float4(
                 0.5462742152960396f * (xx - yy),
                 0.5900435899266435f * y * (-3.0f * xx + yy),
                 2.890611442640554f * xy * z,
                 0.4570457994644657f * y * (1.0f - 5.0f * zz));
            *(float4*)(frow + 76) = make_float4(
                 0.3731763325901154f * z * (5.0f * zz - 3.0f),
                 0.4570457994644657f * x * (1.0f - 5.0f * zz),
                 1.445305721320277f * z * (xx - yy),
                 0.5900435899266435f * x * (xx - 3.0f * yy));
        }
        __syncwarp();

        // ---------- color MLP with pipelined gathers for tile wt+STRIDE ----------
        u64 ebA[16], ebB[16];

        // C1 reads SH+dout from X (inoff=64); issue g0,g1 during C1
        layer_relu<32, 64>(wf + WF_C1, bias + 80, Aw, lane, 64, [&](int m) {
            if (have_next && m == 0) {
                issue2(emb, 0, cxn, cyn, czn, ebA);
                issue2(emb, 1, cxn, cyn, czn, ebB);
            }
        });
        // consumes may write X only after C1 m1 has read it
        layer_relu<64, 64>(wf + WF_C2, bias + 144, Aw, lane, 0, [&](int m) {
            if (!have_next) return;
            if (m == 0) { consume2(0, ebA, cxn, cyn, czn, frow); issue2(emb, 2, cxn, cyn, czn, ebA); }
            else        { consume2(1, ebB, cxn, cyn, czn, frow); issue2(emb, 3, cxn, cyn, czn, ebB); }
        });
        layer_relu<64, 64>(wf + WF_C3, bias + 208, Aw, lane, 0, [&](int m) {
            if (!have_next) return;
            if (m == 0) { consume2(2, ebA, cxn, cyn, czn, frow); issue2(emb, 4, cxn, cyn, czn, ebA); }
            else        { consume2(3, ebB, cxn, cyn, czn, frow); issue2(emb, 5, cxn, cyn, czn, ebB); }
        });
        layer_c4(wf + WF_C4, bias + 272, Aw, lane, out, wt * 32, [&](int m) {
            if (!have_next) return;
            if (m == 0) { consume2(4, ebA, cxn, cyn, czn, frow); issue2(emb, 6, cxn, cyn, czn, ebA); }
            else        { consume2(5, ebB, cxn, cyn, czn, frow); issue2(emb, 7, cxn, cyn, czn, ebB); }
        });

        if (have_next) {
            consume2(6, ebA, cxn, cyn, czn, frow);
            consume2(7, ebB, cxn, cyn, czn, frow);
        }
        __syncwarp();   // X complete before next tile's D-L1 cross-lane reads
    }
}

extern "C" void kernel_launch(void* const* d_in, const int* in_sizes, int n_in,
                              void* d_out, int out_size)
{
    const float* coords = (const float*)d_in[0];
    const float* dirs   = (const float*)d_in[1];
    const u64*   emb    = (const u64*)d_in[2];
    const float* dw1 = (const float*)d_in[3];
    const float* db1 = (const float*)d_in[4];
    const float* dw2 = (const float*)d_in[5];
    const float* db2 = (const float*)d_in[6];
    const float* cw1 = (const float*)d_in[7];
    const float* cb1 = (const float*)d_in[8];
    const float* cw2 = (const float*)d_in[9];
    const float* cb2 = (const float*)d_in[10];
    const float* cw3 = (const float*)d_in[11];
    const float* cb3 = (const float*)d_in[12];
    const float* cw4 = (const float*)d_in[13];
    const float* cb4 = (const float*)d_in[14];
    float* out = (float*)d_out;

    cudaFuncSetAttribute(nerf_mma_kernel,
                         cudaFuncAttributeMaxDynamicSharedMemorySize, SMEM_BYTES);

    nerf_mma_kernel<<<NCTA, THREADS, SMEM_BYTES>>>(
        coords, dirs, emb,
        dw1, db1, dw2, db2,
        cw1, cb1, cw2, cb2, cw3, cb3, cw4, cb4,
        out);
}

// round 14
// speedup vs baseline: 1.5239x; 1.5239x over previous
#include <cuda_runtime.h>
#include <stdint.h>

#define NPTS    262144
#define NWTILES 8192          // warp-tiles of 32 points
#define TMASK   0x7FFFFu
#define RS      72            // staging row stride (floats); conflict-free A-frag loads
#define THREADS 448
#define NWARP   14
#define NCTA    148

// weight fragment arrays (uint4 units)
#define WF_L1 0               // Kt2 Nt8 -> 512
#define WF_L2 512             // Kt4 Nt2 -> 256
#define WF_C1 768             // Kt2 Nt8 -> 512
#define WF_C2 1280            // Kt4 Nt8 -> 1024
#define WF_C3 2304            // Kt4 Nt8 -> 1024
#define WF_C4 3328            // Kt4 Nt1 -> 128
#define WF_TOT 3456
#define BIAS_F (WF_TOT * 4)   // float idx 13824
#define STG_F  (BIAS_F + 280) // 14104, 16B aligned
#define SMEM_FLOATS (STG_F + NWARP * 32 * RS)
#define SMEM_BYTES  (SMEM_FLOATS * 4)   // 185,440 B

typedef unsigned long long u64;

__constant__ float RESV[16] = {16.f, 20.f, 25.f, 32.f, 40.f, 50.f, 64.f, 80.f,
                               101.f, 128.f, 161.f, 203.f, 256.f, 322.f, 406.f, 512.f};

__device__ __forceinline__ uint32_t pkb(float lo, float hi) {
    uint32_t r; asm("cvt.rn.bf16x2.f32 %0, %1, %2;" : "=r"(r) : "f"(hi), "f"(lo)); return r;
}
__device__ __forceinline__ float lof(uint32_t u) { return __uint_as_float(u << 16); }
__device__ __forceinline__ float hif(uint32_t u) { return __uint_as_float(u & 0xffff0000u); }

__device__ __forceinline__ void mma16(float* d, const uint32_t* a, uint32_t b0, uint32_t b1) {
    asm volatile(
        "mma.sync.aligned.m16n8k16.row.col.f32.bf16.bf16.f32 "
        "{%0,%1,%2,%3},{%4,%5,%6,%7},{%8,%9},{%0,%1,%2,%3};"
        : "+f"(d[0]), "+f"(d[1]), "+f"(d[2]), "+f"(d[3])
        : "r"(a[0]), "r"(a[1]), "r"(a[2]), "r"(a[3]), "r"(b0), "r"(b1));
}

// acc[Nt][4] = A(16xK fp32 staging) @ W(KxN), 3-pass bf16 (AhBh + AlBh + AhBl)
template<int K, int N>
__device__ __forceinline__ void mma_compute(const uint4* __restrict__ Wf,
                                            const float* __restrict__ Aw,
                                            int m, int lane, float acc[N / 8][4])
{
    constexpr int Kt = K / 16, Nt = N / 8;
    const int g = lane >> 2, tig = lane & 3;
#pragma unroll
    for (int nt = 0; nt < Nt; nt++)
        acc[nt][0] = acc[nt][1] = acc[nt][2] = acc[nt][3] = 0.f;
    const float* base = Aw + (16 * m + g) * RS + 2 * tig;
#pragma unroll
    for (int kt = 0; kt < Kt; kt++) {
        const float* ar = base + kt * 16;
        float2 va = *(const float2*)(ar);
        float2 vc = *(const float2*)(ar + 8 * RS);
        float2 vb = *(const float2*)(ar + 8);
        float2 vd = *(const float2*)(ar + 8 * RS + 8);
        uint32_t ah[4], al[4];
        ah[0] = pkb(va.x, va.y); al[0] = pkb(va.x - lof(ah[0]), va.y - hif(ah[0]));
        ah[1] = pkb(vc.x, vc.y); al[1] = pkb(vc.x - lof(ah[1]), vc.y - hif(ah[1]));
        ah[2] = pkb(vb.x, vb.y); al[2] = pkb(vb.x - lof(ah[2]), vb.y - hif(ah[2]));
        ah[3] = pkb(vd.x, vd.y); al[3] = pkb(vd.x - lof(ah[3]), vd.y - hif(ah[3]));
#pragma unroll
        for (int nt = 0; nt < Nt; nt++) {
            uint4 B = Wf[(nt * Kt + kt) * 32 + lane];
            mma16(acc[nt], ah, B.x, B.y);
            mma16(acc[nt], al, B.x, B.y);
            mma16(acc[nt], ah, B.z, B.w);
        }
    }
}

template<int K, int N>
__device__ __forceinline__ void layer_relu(const uint4* __restrict__ Wf,
                                           const float* __restrict__ bias,
                                           float* __restrict__ Aw, int lane)
{
    constexpr int Nt = N / 8;
    const int g = lane >> 2, tig = lane & 3;
#pragma unroll
    for (int m = 0; m < 2; m++) {
        float acc[Nt][4];
        mma_compute<K, N>(Wf, Aw, m, lane, acc);
        __syncwarp();
        float* s0 = Aw + (16 * m + g) * RS + 2 * tig;
#pragma unroll
        for (int nt = 0; nt < Nt; nt++) {
            float b0 = bias[nt * 8 + 2 * tig], b1 = bias[nt * 8 + 2 * tig + 1];
            *(float2*)(s0 + nt * 8) =
                make_float2(fmaxf(acc[nt][0] + b0, 0.f), fmaxf(acc[nt][1] + b1, 0.f));
            *(float2*)(s0 + 8 * RS + nt * 8) =
                make_float2(fmaxf(acc[nt][2] + b0, 0.f), fmaxf(acc[nt][3] + b1, 0.f));
        }
        // no sync: m1 reads rows 16..31, disjoint from m0's stores
    }
    __syncwarp();
}

// density layer 2: 64 -> 16, no relu, writes cols 16..31
__device__ __forceinline__ void layer_l2(const uint4* __restrict__ Wf,
                                         const float* __restrict__ bias,
                                         float* __restrict__ Aw, int lane)
{
    const int g = lane >> 2, tig = lane & 3;
#pragma unroll
    for (int m = 0; m < 2; m++) {
        float acc[2][4];
        mma_compute<64, 16>(Wf, Aw, m, lane, acc);
        __syncwarp();
        float* s0 = Aw + (16 * m + g) * RS + 16 + 2 * tig;
#pragma unroll
        for (int nt = 0; nt < 2; nt++) {
            float b0 = bias[nt * 8 + 2 * tig], b1 = bias[nt * 8 + 2 * tig + 1];
            *(float2*)(s0 + nt * 8) = make_float2(acc[nt][0] + b0, acc[nt][1] + b1);
            *(float2*)(s0 + 8 * RS + nt * 8) = make_float2(acc[nt][2] + b0, acc[nt][3] + b1);
        }
    }
    __syncwarp();
}

__device__ __forceinline__ float sigm(float v) { return 1.f / (1.f + expf(-v)); }

__device__ __forceinline__ void layer_c4(const uint4* __restrict__ Wf,
                                         const float* __restrict__ bias,
                                         const float* __restrict__ Aw, int lane,
                                         float* __restrict__ out, int pbase)
{
    const int g = lane >> 2, tig = lane & 3;
#pragma unroll
    for (int m = 0; m < 2; m++) {
        float acc[1][4];
        mma_compute<64, 8>(Wf, Aw, m, lane, acc);
        int r0 = pbase + 16 * m + g;
        int c = 2 * tig;
        if (c < 3) {
            float b = bias[c];
            out[NPTS + 3 * r0 + c]       = sigm(acc[0][0] + b);
            out[NPTS + 3 * (r0 + 8) + c] = sigm(acc[0][2] + b);
        }
        if (c + 1 < 3) {
            float b = bias[c + 1];
            out[NPTS + 3 * r0 + c + 1]       = sigm(acc[0][1] + b);
            out[NPTS + 3 * (r0 + 8) + c + 1] = sigm(acc[0][3] + b);
        }
    }
    __syncwarp();
}

__device__ __forceinline__ void stage_w(uint4* __restrict__ dst, const float* __restrict__ w,
                                        int Kt, int Nt, int rN, int tid)
{
    int tot = Kt * Nt * 32;
    for (int idx = tid; idx < tot; idx += THREADS) {
        int lane = idx & 31, f = idx >> 5;
        int kt = f % Kt, nt = f / Kt;
        int g = lane >> 2, tig = lane & 3;
        int n = nt * 8 + g;
        int k0 = kt * 16 + 2 * tig;
        float w00 = 0.f, w01 = 0.f, w10 = 0.f, w11 = 0.f;
        if (n < rN) {
            w00 = w[k0 * rN + n];       w01 = w[(k0 + 1) * rN + n];
            w10 = w[(k0 + 8) * rN + n]; w11 = w[(k0 + 9) * rN + n];
        }
        uint32_t h0 = pkb(w00, w01), h1 = pkb(w10, w11);
        uint32_t l0 = pkb(w00 - lof(h0), w01 - hif(h0));
        uint32_t l1 = pkb(w10 - lof(h1), w11 - hif(h1));
        dst[idx] = make_uint4(h0, h1, l0, l1);
    }
}

__global__ void __launch_bounds__(THREADS, 1)
nerf_mma_kernel(const float* __restrict__ coords,
                const float* __restrict__ dirs,
                const u64*   __restrict__ emb,
                const float* __restrict__ dw1, const float* __restrict__ db1,
                const float* __restrict__ dw2, const float* __restrict__ db2,
                const float* __restrict__ cw1, const float* __restrict__ cb1,
                const float* __restrict__ cw2, const float* __restrict__ cb2,
                const float* __restrict__ cw3, const float* __restrict__ cb3,
                const float* __restrict__ cw4, const float* __restrict__ cb4,
                float* __restrict__ out)
{
    extern __shared__ float sm[];
    uint4* wf = (uint4*)sm;
    const int tid = threadIdx.x;

    stage_w(wf + WF_L1, dw1, 2, 8, 64, tid);
    stage_w(wf + WF_L2, dw2, 4, 2, 16, tid);
    stage_w(wf + WF_C1, cw1, 2, 8, 64, tid);
    stage_w(wf + WF_C2, cw2, 4, 8, 64, tid);
    stage_w(wf + WF_C3, cw3, 4, 8, 64, tid);
    stage_w(wf + WF_C4, cw4, 4, 1,  3, tid);
    for (int i = tid; i < 64; i += THREADS) sm[BIAS_F + i] = db1[i];
    for (int i = tid; i < 16; i += THREADS) sm[BIAS_F + 64 + i] = db2[i];
    for (int i = tid; i < 64; i += THREADS) sm[BIAS_F + 80 + i] = cb1[i];
    for (int i = tid; i < 64; i += THREADS) sm[BIAS_F + 144 + i] = cb2[i];
    for (int i = tid; i < 64; i += THREADS) sm[BIAS_F + 208 + i] = cb3[i];
    for (int i = tid; i < 8;  i += THREADS) sm[BIAS_F + 272 + i] = (i < 3) ? cb4[i] : 0.f;
    __syncthreads();

    const int lane = tid & 31, warp = tid >> 5;
    float* Aw = sm + STG_F + warp * (32 * RS);
    float* frow = Aw + lane * RS;

    for (int wt = blockIdx.x * NWARP + warp; wt < NWTILES; wt += NCTA * NWARP) {
        const int p = wt * 32 + lane;

        // ---------- hash-grid encode, 2-level load batching (low reg footprint) ----------
        const float cx = coords[3 * p + 0];
        const float cy = coords[3 * p + 1];
        const float cz = coords[3 * p + 2];

#pragma unroll
        for (int lg = 0; lg < 8; lg++) {
            u64 eb[16];
            // phase 1: issue the 16 gathers of levels 2lg, 2lg+1
#pragma unroll
            for (int j = 0; j < 2; j++) {
                const int l = lg * 2 + j;
                const float r = RESV[l];
                uint32_t px = (uint32_t)floorf(cx * r);
                uint32_t py = (uint32_t)floorf(cy * r);
                uint32_t pz = (uint32_t)floorf(cz * r);
                uint32_t hx0 = px,                hx1 = px + 1u;
                uint32_t hy0 = py * 2654435761u,  hy1 = hy0 + 2654435761u;
                uint32_t hz0 = pz * 805459861u,   hz1 = hz0 + 805459861u;
                const u64* tt = emb + ((size_t)l << 19);
                eb[8 * j + 0] = __ldg(tt + ((hx0 ^ hy0 ^ hz0) & TMASK));
                eb[8 * j + 1] = __ldg(tt + ((hx0 ^ hy0 ^ hz1) & TMASK));
                eb[8 * j + 2] = __ldg(tt + ((hx0 ^ hy1 ^ hz0) & TMASK));
                eb[8 * j + 3] = __ldg(tt + ((hx0 ^ hy1 ^ hz1) & TMASK));
                eb[8 * j + 4] = __ldg(tt + ((hx1 ^ hy0 ^ hz0) & TMASK));
                eb[8 * j + 5] = __ldg(tt + ((hx1 ^ hy0 ^ hz1) & TMASK));
                eb[8 * j + 6] = __ldg(tt + ((hx1 ^ hy1 ^ hz0) & TMASK));
                eb[8 * j + 7] = __ldg(tt + ((hx1 ^ hy1 ^ hz1) & TMASK));
            }
            // phase 2: interpolate
#pragma unroll
            for (int j = 0; j < 2; j++) {
                const int l = lg * 2 + j;
                const float r = RESV[l];
                float fx = cx * r, fy = cy * r, fz = cz * r;
                float tx = fx - floorf(fx), ty = fy - floorf(fy), tz = fz - floorf(fz);
                float ux = 1.f - tx, uy = 1.f - ty, uz = 1.f - tz;
                float w00 = ux * uy, w01 = ux * ty, w10 = tx * uy, w11 = tx * ty;
                float2 v; float a0 = 0.f, a1 = 0.f, w;
                w = w00 * uz; v = *(float2*)&eb[8 * j + 0]; a0 = fmaf(w, v.x, a0); a1 = fmaf(w, v.y, a1);
                w = w00 * tz; v = *(float2*)&eb[8 * j + 1]; a0 = fmaf(w, v.x, a0); a1 = fmaf(w, v.y, a1);
                w = w01 * uz; v = *(float2*)&eb[8 * j + 2]; a0 = fmaf(w, v.x, a0); a1 = fmaf(w, v.y, a1);
                w = w01 * tz; v = *(float2*)&eb[8 * j + 3]; a0 = fmaf(w, v.x, a0); a1 = fmaf(w, v.y, a1);
                w = w10 * uz; v = *(float2*)&eb[8 * j + 4]; a0 = fmaf(w, v.x, a0); a1 = fmaf(w, v.y, a1);
                w = w10 * tz; v = *(float2*)&eb[8 * j + 5]; a0 = fmaf(w, v.x, a0); a1 = fmaf(w, v.y, a1);
                w = w11 * uz; v = *(float2*)&eb[8 * j + 6]; a0 = fmaf(w, v.x, a0); a1 = fmaf(w, v.y, a1);
                w = w11 * tz; v = *(float2*)&eb[8 * j + 7]; a0 = fmaf(w, v.x, a0); a1 = fmaf(w, v.y, a1);
                *(float2*)(frow + 2 * l) = make_float2(a0, a1);
            }
        }
        __syncwarp();

        // ---------- density MLP ----------
        layer_relu<32, 64>(wf + WF_L1, sm + BIAS_F, Aw, lane);
        layer_l2(wf + WF_L2, sm + BIAS_F + 64, Aw, lane);

        out[p] = expf(frow[16]);

        // ---------- SH deg-4 into cols 0..15 (dirs loaded here, not held) ----------
        {
            float dxr = dirs[3 * p + 0];
            float dyr = dirs[3 * p + 1];
            float dzr = dirs[3 * p + 2];
            float nrm = sqrtf(dxr * dxr + dyr * dyr + dzr * dzr);
            float x = dxr / nrm, y = dyr / nrm, z = dzr / nrm;
            x = ((x + 1.f) * 0.5f) * 2.f - 1.f;
            y = ((y + 1.f) * 0.5f) * 2.f - 1.f;
            z = ((z + 1.f) * 0.5f) * 2.f - 1.f;
            float xx = x * x, yy = y * y, zz = z * z;
            float xy = x * y, yz = y * z, xz = x * z;
            *(float4*)(frow + 0) = make_float4(
                0.28209479177387814f,
                -0.48860251190291987f * y,
                 0.48860251190291987f * z,
                -0.48860251190291987f * x);
            *(float4*)(frow + 4) = make_float4(
                 1.0925484305920792f * xy,
                -1.0925484305920792f * yz,
                 0.94617469575756f * zz - 0.31539156525252f,
                -1.0925484305920792f * xz);
            *(float4*)(frow + 8) = make_float4(
                 0.5462742152960396f * (xx - yy),
                 0.5900435899266435f * y * (-3.0f * xx + yy),
                 2.890611442640554f * xy * z,
                 0.4570457994644657f * y * (1.0f - 5.0f * zz));
            *(float4*)(frow + 12) = make_float4(
                 0.3731763325901154f * z * (5.0f * zz - 3.0f),
                 0.4570457994644657f * x * (1.0f - 5.0f * zz),
                 1.445305721320277f * z * (xx - yy),
                 0.5900435899266435f * x * (xx - 3.0f * yy));
        }
        __syncwarp();

        // ---------- color MLP ----------
        layer_relu<32, 64>(wf + WF_C1, sm + BIAS_F + 80,  Aw, lane);
        layer_relu<64, 64>(wf + WF_C2, sm + BIAS_F + 144, Aw, lane);
        layer_relu<64, 64>(wf + WF_C3, sm + BIAS_F + 208, Aw, lane);
        layer_c4(wf + WF_C4, sm + BIAS_F + 272, Aw, lane, out, wt * 32);
    }
}

extern "C" void kernel_launch(void* const* d_in, const int* in_sizes, int n_in,
                              void* d_out, int out_size)
{
    const float* coords = (const float*)d_in[0];
    const float* dirs   = (const float*)d_in[1];
    const u64*   emb    = (const u64*)d_in[2];
    const float* dw1 = (const float*)d_in[3];
    const float* db1 = (const float*)d_in[4];
    const float* dw2 = (const float*)d_in[5];
    const float* db2 = (const float*)d_in[6];
    const float* cw1 = (const float*)d_in[7];
    const float* cb1 = (const float*)d_in[8];
    const float* cw2 = (const float*)d_in[9];
    const float* cb2 = (const float*)d_in[10];
    const float* cw3 = (const float*)d_in[11];
    const float* cb3 = (const float*)d_in[12];
    const float* cw4 = (const float*)d_in[13];
    const float* cb4 = (const float*)d_in[14];
    float* out = (float*)d_out;

    cudaFuncSetAttribute(nerf_mma_kernel,
                         cudaFuncAttributeMaxDynamicSharedMemorySize, SMEM_BYTES);

    nerf_mma_kernel<<<NCTA, THREADS, SMEM_BYTES>>>(
        coords, dirs, emb,
        dw1, db1, dw2, db2,
        cw1, cb1, cw2, cb2, cw3, cb3, cw4, cb4,
        out);
}

// round 15
// speedup vs baseline: 1.8792x; 1.2332x over previous
#include <cuda_runtime.h>
#include <stdint.h>

#define NPTS    262144
#define NWTILES 8192          // warp-tiles of 32 points
#define TMASK   0x7FFFFu
#define RS      72            // staging row stride (32-bit words); conflict-free frag loads
#define THREADS 384
#define NWARP   12
#define NCTA    148

// weight fragment arrays (uint4 units)
#define WF_L1 0               // Kt2 Nt8 -> 512
#define WF_L2 512             // Kt4 Nt2 -> 256
#define WF_C1 768             // Kt2 Nt8 -> 512
#define WF_C2 1280            // Kt4 Nt8 -> 1024
#define WF_C3 2304            // Kt4 Nt8 -> 1024
#define WF_C4 3328            // Kt4 Nt1 -> 128
#define WF_TOT 3456
#define BIAS_F (WF_TOT * 4)   // float idx 13824
#define STG_F  (BIAS_F + 280) // 14104, 16B aligned
#define SMEM_FLOATS (STG_F + NWARP * 32 * RS)
#define SMEM_BYTES  (SMEM_FLOATS * 4)

typedef unsigned long long u64;

__device__ __forceinline__ uint32_t pkb(float lo, float hi) {
    uint32_t r; asm("cvt.rn.bf16x2.f32 %0, %1, %2;" : "=r"(r) : "f"(hi), "f"(lo)); return r;
}
__device__ __forceinline__ float lof(uint32_t u) { return __uint_as_float(u << 16); }
__device__ __forceinline__ float hif(uint32_t u) { return __uint_as_float(u & 0xffff0000u); }

// pack two fp32 into {hi_pair, lo_pair} bf16x2 words (3-pass-split representation)
__device__ __forceinline__ uint2 pksplit(float v0, float v1) {
    uint32_t h = pkb(v0, v1);
    uint32_t l = pkb(v0 - lof(h), v1 - hif(h));
    return make_uint2(h, l);
}

__device__ __forceinline__ void mma16(float* d, const uint32_t* a, uint32_t b0, uint32_t b1) {
    asm volatile(
        "mma.sync.aligned.m16n8k16.row.col.f32.bf16.bf16.f32 "
        "{%0,%1,%2,%3},{%4,%5,%6,%7},{%8,%9},{%0,%1,%2,%3};"
        : "+f"(d[0]), "+f"(d[1]), "+f"(d[2]), "+f"(d[3])
        : "r"(a[0]), "r"(a[1]), "r"(a[2]), "r"(a[3]), "r"(b0), "r"(b1));
}

// acc[Nt][4] = A(16xK, pre-split bf16 hi/lo pairs in staging) @ W(KxN), 3-pass bf16.
// Staging layout per row: k-pair q stored as uint2 {hi,lo} at words [2q, 2q+1].
template<int K, int N>
__device__ __forceinline__ void mma_compute(const uint4* __restrict__ Wf,
                                            const uint32_t* __restrict__ AwW,
                                            int m, int lane, float acc[N / 8][4])
{
    constexpr int Kt = K / 16, Nt = N / 8;
    const int g = lane >> 2, tig = lane & 3;
#pragma unroll
    for (int nt = 0; nt < Nt; nt++)
        acc[nt][0] = acc[nt][1] = acc[nt][2] = acc[nt][3] = 0.f;
    const uint2* r0 = (const uint2*)(AwW + (16 * m + g) * RS) + tig;
    const uint2* r1 = (const uint2*)(AwW + (16 * m + g + 8) * RS) + tig;
#pragma unroll
    for (int kt = 0; kt < Kt; kt++) {
        uint2 p0 = r0[kt * 8];       // row g,   k-pair kt*8+tig
        uint2 p1 = r1[kt * 8];       // row g+8
        uint2 p2 = r0[kt * 8 + 4];   // row g,   k-pair kt*8+tig+4
        uint2 p3 = r1[kt * 8 + 4];   // row g+8
        uint32_t ah[4] = {p0.x, p1.x, p2.x, p3.x};
        uint32_t al[4] = {p0.y, p1.y, p2.y, p3.y};
#pragma unroll
        for (int nt = 0; nt < Nt; nt++) {
            uint4 B = Wf[(nt * Kt + kt) * 32 + lane];
            mma16(acc[nt], ah, B.x, B.y);
            mma16(acc[nt], al, B.x, B.y);
            mma16(acc[nt], ah, B.z, B.w);
        }
    }
}

// relu layer: writes relu(acc+bias) as pre-split pairs to k-pairs 0..N/2-1
template<int K, int N>
__device__ __forceinline__ void layer_relu(const uint4* __restrict__ Wf,
                                           const float* __restrict__ bias,
                                           uint32_t* __restrict__ AwW, int lane)
{
    constexpr int Nt = N / 8;
    const int g = lane >> 2, tig = lane & 3;
#pragma unroll
    for (int m = 0; m < 2; m++) {
        float acc[Nt][4];
        mma_compute<K, N>(Wf, AwW, m, lane, acc);
        __syncwarp();
        uint32_t* s0 = AwW + (16 * m + g) * RS + 2 * tig;
#pragma unroll
        for (int nt = 0; nt < Nt; nt++) {
            float b0 = bias[nt * 8 + 2 * tig], b1 = bias[nt * 8 + 2 * tig + 1];
            *(uint2*)(s0 + nt * 8) =
                pksplit(fmaxf(acc[nt][0] + b0, 0.f), fmaxf(acc[nt][1] + b1, 0.f));
            *(uint2*)(s0 + 8 * RS + nt * 8) =
                pksplit(fmaxf(acc[nt][2] + b0, 0.f), fmaxf(acc[nt][3] + b1, 0.f));
        }
        // no sync: m1 reads rows 16..31, disjoint from m0's stores
    }
    __syncwarp();
}

// density layer 2: 64 -> 16, no relu, writes pairs to k-pairs 8..15 (words 16..31)
__device__ __forceinline__ void layer_l2(const uint4* __restrict__ Wf,
                                         const float* __restrict__ bias,
                                         uint32_t* __restrict__ AwW, int lane)
{
    const int g = lane >> 2, tig = lane & 3;
#pragma unroll
    for (int m = 0; m < 2; m++) {
        float acc[2][4];
        mma_compute<64, 16>(Wf, AwW, m, lane, acc);
        __syncwarp();
        uint32_t* s0 = AwW + (16 * m + g) * RS + 16 + 2 * tig;
#pragma unroll
        for (int nt = 0; nt < 2; nt++) {
            float b0 = bias[nt * 8 + 2 * tig], b1 = bias[nt * 8 + 2 * tig + 1];
            *(uint2*)(s0 + nt * 8) = pksplit(acc[nt][0] + b0, acc[nt][1] + b1);
            *(uint2*)(s0 + 8 * RS + nt * 8) = pksplit(acc[nt][2] + b0, acc[nt][3] + b1);
        }
    }
    __syncwarp();
}

__device__ __forceinline__ float sigm(float v) { return 1.f / (1.f + expf(-v)); }

__device__ __forceinline__ void layer_c4(const uint4* __restrict__ Wf,
                                         const float* __restrict__ bias,
                                         const uint32_t* __restrict__ AwW, int lane,
                                         float* __restrict__ out, int pbase)
{
    const int g = lane >> 2, tig = lane & 3;
#pragma unroll
    for (int m = 0; m < 2; m++) {
        float acc[1][4];
        mma_compute<64, 8>(Wf, AwW, m, lane, acc);
        int r0 = pbase + 16 * m + g;
        int c = 2 * tig;
        if (c < 3) {
            float b = bias[c];
            out[NPTS + 3 * r0 + c]       = sigm(acc[0][0] + b);
            out[NPTS + 3 * (r0 + 8) + c] = sigm(acc[0][2] + b);
        }
        if (c + 1 < 3) {
            float b = bias[c + 1];
            out[NPTS + 3 * r0 + c + 1]       = sigm(acc[0][1] + b);
            out[NPTS + 3 * (r0 + 8) + c + 1] = sigm(acc[0][3] + b);
        }
    }
    __syncwarp();   // protect staging reads from next tile's feature stores
}

__device__ __forceinline__ void stage_w(uint4* __restrict__ dst, const float* __restrict__ w,
                                        int Kt, int Nt, int rN, int tid)
{
    int tot = Kt * Nt * 32;
    for (int idx = tid; idx < tot; idx += THREADS) {
        int lane = idx & 31, f = idx >> 5;
        int kt = f % Kt, nt = f / Kt;
        int g = lane >> 2, tig = lane & 3;
        int n = nt * 8 + g;
        int k0 = kt * 16 + 2 * tig;
        float w00 = 0.f, w01 = 0.f, w10 = 0.f, w11 = 0.f;
        if (n < rN) {
            w00 = w[k0 * rN + n];       w01 = w[(k0 + 1) * rN + n];
            w10 = w[(k0 + 8) * rN + n]; w11 = w[(k0 + 9) * rN + n];
        }
        uint32_t h0 = pkb(w00, w01), h1 = pkb(w10, w11);
        uint32_t l0 = pkb(w00 - lof(h0), w01 - hif(h0));
        uint32_t l1 = pkb(w10 - lof(h1), w11 - hif(h1));
        dst[idx] = make_uint4(h0, h1, l0, l1);
    }
}

__global__ void __launch_bounds__(THREADS, 1)
nerf_mma_kernel(const float* __restrict__ coords,
                const float* __restrict__ dirs,
                const u64*   __restrict__ emb,
                const float* __restrict__ dw1, const float* __restrict__ db1,
                const float* __restrict__ dw2, const float* __restrict__ db2,
                const float* __restrict__ cw1, const float* __restrict__ cb1,
                const float* __restrict__ cw2, const float* __restrict__ cb2,
                const float* __restrict__ cw3, const float* __restrict__ cb3,
                const float* __restrict__ cw4, const float* __restrict__ cb4,
                float* __restrict__ out)
{
    extern __shared__ float sm[];
    uint4* wf = (uint4*)sm;
    const int tid = threadIdx.x;

    stage_w(wf + WF_L1, dw1, 2, 8, 64, tid);
    stage_w(wf + WF_L2, dw2, 4, 2, 16, tid);
    stage_w(wf + WF_C1, cw1, 2, 8, 64, tid);
    stage_w(wf + WF_C2, cw2, 4, 8, 64, tid);
    stage_w(wf + WF_C3, cw3, 4, 8, 64, tid);
    stage_w(wf + WF_C4, cw4, 4, 1,  3, tid);
    for (int i = tid; i < 64; i += THREADS) sm[BIAS_F + i] = db1[i];
    for (int i = tid; i < 16; i += THREADS) sm[BIAS_F + 64 + i] = db2[i];
    for (int i = tid; i < 64; i += THREADS) sm[BIAS_F + 80 + i] = cb1[i];
    for (int i = tid; i < 64; i += THREADS) sm[BIAS_F + 144 + i] = cb2[i];
    for (int i = tid; i < 64; i += THREADS) sm[BIAS_F + 208 + i] = cb3[i];
    for (int i = tid; i < 8;  i += THREADS) sm[BIAS_F + 272 + i] = (i < 3) ? cb4[i] : 0.f;
    __syncthreads();

    const int lane = tid & 31, warp = tid >> 5;
    uint32_t* AwW = (uint32_t*)(sm + STG_F) + warp * (32 * RS);
    uint32_t* frowW = AwW + lane * RS;
    const float* bias = sm + BIAS_F;

    const float RESV[16] = {16.f, 20.f, 25.f, 32.f, 40.f, 50.f, 64.f, 80.f,
                            101.f, 128.f, 161.f, 203.f, 256.f, 322.f, 406.f, 512.f};

    for (int wt = blockIdx.x * NWARP + warp; wt < NWTILES; wt += NCTA * NWARP) {
        const int p = wt * 32 + lane;

        // ---------- hash-grid encode (1 point per lane); pair l -> words [2l, 2l+1] ----
        const float cx = coords[3 * p + 0];
        const float cy = coords[3 * p + 1];
        const float cz = coords[3 * p + 2];
        float dxr = dirs[3 * p + 0];
        float dyr = dirs[3 * p + 1];
        float dzr = dirs[3 * p + 2];

#pragma unroll
        for (int l = 0; l < 16; l++) {
            const float r = RESV[l];
            float fx = cx * r, fy = cy * r, fz = cz * r;
            float xf = floorf(fx), yf = floorf(fy), zf = floorf(fz);
            float tx = fx - xf, ty = fy - yf, tz = fz - zf;
            uint32_t px = (uint32_t)xf, py = (uint32_t)yf, pz = (uint32_t)zf;
            uint32_t hx0 = px,                hx1 = px + 1u;
            uint32_t hy0 = py * 2654435761u,  hy1 = hy0 + 2654435761u;
            uint32_t hz0 = pz * 805459861u,   hz1 = hz0 + 805459861u;
            const u64* tt = emb + ((size_t)l << 19);
            u64 e000 = __ldg(tt + ((hx0 ^ hy0 ^ hz0) & TMASK));
            u64 e001 = __ldg(tt + ((hx0 ^ hy0 ^ hz1) & TMASK));
            u64 e010 = __ldg(tt + ((hx0 ^ hy1 ^ hz0) & TMASK));
            u64 e011 = __ldg(tt + ((hx0 ^ hy1 ^ hz1) & TMASK));
            u64 e100 = __ldg(tt + ((hx1 ^ hy0 ^ hz0) & TMASK));
            u64 e101 = __ldg(tt + ((hx1 ^ hy0 ^ hz1) & TMASK));
            u64 e110 = __ldg(tt + ((hx1 ^ hy1 ^ hz0) & TMASK));
            u64 e111 = __ldg(tt + ((hx1 ^ hy1 ^ hz1) & TMASK));

            float ux = 1.f - tx, uy = 1.f - ty, uz = 1.f - tz;
            float w00 = ux * uy, w01 = ux * ty, w10 = tx * uy, w11 = tx * ty;
            float2 v; float a0 = 0.f, a1 = 0.f, w;
            w = w00 * uz; v = *(float2*)&e000; a0 = fmaf(w, v.x, a0); a1 = fmaf(w, v.y, a1);
            w = w00 * tz; v = *(float2*)&e001; a0 = fmaf(w, v.x, a0); a1 = fmaf(w, v.y, a1);
            w = w01 * uz; v = *(float2*)&e010; a0 = fmaf(w, v.x, a0); a1 = fmaf(w, v.y, a1);
            w = w01 * tz; v = *(float2*)&e011; a0 = fmaf(w, v.x, a0); a1 = fmaf(w, v.y, a1);
            w = w10 * uz; v = *(float2*)&e100; a0 = fmaf(w, v.x, a0); a1 = fmaf(w, v.y, a1);
            w = w10 * tz; v = *(float2*)&e101; a0 = fmaf(w, v.x, a0); a1 = fmaf(w, v.y, a1);
            w = w11 * uz; v = *(float2*)&e110; a0 = fmaf(w, v.x, a0); a1 = fmaf(w, v.y, a1);
            w = w11 * tz; v = *(float2*)&e111; a0 = fmaf(w, v.x, a0); a1 = fmaf(w, v.y, a1);
            *(uint2*)(frowW + 2 * l) = pksplit(a0, a1);
        }
        __syncwarp();

        // ---------- density MLP ----------
        layer_relu<32, 64>(wf + WF_L1, bias, AwW, lane);
        layer_l2(wf + WF_L2, bias + 64, AwW, lane);   // dout -> pairs 8..15

        // density = exp(dout[0]); dout[0] = hi+lo of pair 8's low halves
        out[p] = expf(lof(frowW[16]) + lof(frowW[17]));

        // ---------- SH deg-4 into pairs 0..7 (words 0..15) ----------
        {
            float nrm = sqrtf(dxr * dxr + dyr * dyr + dzr * dzr);
            float x = dxr / nrm, y = dyr / nrm, z = dzr / nrm;
            x = ((x + 1.f) * 0.5f) * 2.f - 1.f;
            y = ((y + 1.f) * 0.5f) * 2.f - 1.f;
            z = ((z + 1.f) * 0.5f) * 2.f - 1.f;
            float xx = x * x, yy = y * y, zz = z * z;
            float xy = x * y, yz = y * z, xz = x * z;
            float s0 = 0.28209479177387814f;
            float s1 = -0.48860251190291987f * y;
            float s2 =  0.48860251190291987f * z;
            float s3 = -0.48860251190291987f * x;
            float s4 =  1.0925484305920792f * xy;
            float s5 = -1.0925484305920792f * yz;
            float s6 =  0.94617469575756f * zz - 0.31539156525252f;
            float s7 = -1.0925484305920792f * xz;
            float s8 =  0.5462742152960396f * (xx - yy);
            float s9 =  0.5900435899266435f * y * (-3.0f * xx + yy);
            float s10 = 2.890611442640554f * xy * z;
            float s11 = 0.4570457994644657f * y * (1.0f - 5.0f * zz);
            float s12 = 0.3731763325901154f * z * (5.0f * zz - 3.0f);
            float s13 = 0.4570457994644657f * x * (1.0f - 5.0f * zz);
            float s14 = 1.445305721320277f * z * (xx - yy);
            float s15 = 0.5900435899266435f * x * (xx - 3.0f * yy);
            *(uint2*)(frowW + 0)  = pksplit(s0,  s1);
            *(uint2*)(frowW + 2)  = pksplit(s2,  s3);
            *(uint2*)(frowW + 4)  = pksplit(s4,  s5);
            *(uint2*)(frowW + 6)  = pksplit(s6,  s7);
            *(uint2*)(frowW + 8)  = pksplit(s8,  s9);
            *(uint2*)(frowW + 10) = pksplit(s10, s11);
            *(uint2*)(frowW + 12) = pksplit(s12, s13);
            *(uint2*)(frowW + 14) = pksplit(s14, s15);
        }
        __syncwarp();

        // ---------- color MLP ----------
        layer_relu<32, 64>(wf + WF_C1, bias + 80,  AwW, lane);
        layer_relu<64, 64>(wf + WF_C2, bias + 144, AwW, lane);
        layer_relu<64, 64>(wf + WF_C3, bias + 208, AwW, lane);
        layer_c4(wf + WF_C4, bias + 272, AwW, lane, out, wt * 32);
    }
}

extern "C" void kernel_launch(void* const* d_in, const int* in_sizes, int n_in,
                              void* d_out, int out_size)
{
    const float* coords = (const float*)d_in[0];
    const float* dirs   = (const float*)d_in[1];
    const u64*   emb    = (const u64*)d_in[2];
    const float* dw1 = (const float*)d_in[3];
    const float* db1 = (const float*)d_in[4];
    const float* dw2 = (const float*)d_in[5];
    const float* db2 = (const float*)d_in[6];
    const float* cw1 = (const float*)d_in[7];
    const float* cb1 = (const float*)d_in[8];
    const float* cw2 = (const float*)d_in[9];
    const float* cb2 = (const float*)d_in[10];
    const float* cw3 = (const float*)d_in[11];
    const float* cb3 = (const float*)d_in[12];
    const float* cw4 = (const float*)d_in[13];
    const float* cb4 = (const float*)d_in[14];
    float* out = (float*)d_out;

    cudaFuncSetAttribute(nerf_mma_kernel,
                         cudaFuncAttributeMaxDynamicSharedMemorySize, SMEM_BYTES);

    nerf_mma_kernel<<<NCTA, THREADS, SMEM_BYTES>>>(
        coords, dirs, emb,
        dw1, db1, dw2, db2,
        cw1, cb1, cw2, cb2, cw3, cb3, cw4, cb4,
        out);
}

// round 16
// speedup vs baseline: 1.9707x; 1.0487x over previous
#include <cuda_runtime.h>
#include <stdint.h>

#define NPTS    262144
#define NWTILES 8192          // warp-tiles of 32 points
#define TMASK   0x7FFFFu
#define RS      72            // staging row stride (floats); conflict-free frag loads
#define THREADS 384
#define NWARP   12
#define NCTA    148

// weight fragment arrays (uint4 units)
#define WF_L1 0               // Kt2 Nt8 -> 512
#define WF_L2 512             // Kt4 Nt2 -> 256
#define WF_C1 768             // Kt2 Nt8 -> 512
#define WF_C2 1280            // Kt4 Nt8 -> 1024
#define WF_C3 2304            // Kt4 Nt8 -> 1024
#define WF_C4 3328            // Kt4 Nt1 -> 128
#define WF_TOT 3456
#define BIAS_F (WF_TOT * 4)   // float idx 13824
#define STG_F  (BIAS_F + 280) // 14104, 16B aligned
#define SMEM_FLOATS (STG_F + NWARP * 32 * RS)
#define SMEM_BYTES  (SMEM_FLOATS * 4)

typedef unsigned long long u64;

__device__ __forceinline__ uint32_t pkb(float lo, float hi) {
    uint32_t r; asm("cvt.rn.bf16x2.f32 %0, %1, %2;" : "=r"(r) : "f"(hi), "f"(lo)); return r;
}
__device__ __forceinline__ float lof(uint32_t u) { return __uint_as_float(u << 16); }
__device__ __forceinline__ float hif(uint32_t u) { return __uint_as_float(u & 0xffff0000u); }

__device__ __forceinline__ void mma16(float* d, const uint32_t* a, uint32_t b0, uint32_t b1) {
    asm volatile(
        "mma.sync.aligned.m16n8k16.row.col.f32.bf16.bf16.f32 "
        "{%0,%1,%2,%3},{%4,%5,%6,%7},{%8,%9},{%0,%1,%2,%3};"
        : "+f"(d[0]), "+f"(d[1]), "+f"(d[2]), "+f"(d[3])
        : "r"(a[0]), "r"(a[1]), "r"(a[2]), "r"(a[3]), "r"(b0), "r"(b1));
}

// acc[Nt][4] = A(16xK fp32 staging) @ W(KxN), 3-pass bf16 (AhBh + AlBh + AhBl)
template<int K, int N>
__device__ __forceinline__ void mma_compute(const uint4* __restrict__ Wf,
                                            const float* __restrict__ Aw,
                                            int m, int lane, float acc[N / 8][4])
{
    constexpr int Kt = K / 16, Nt = N / 8;
    const int g = lane >> 2, tig = lane & 3;
#pragma unroll
    for (int nt = 0; nt < Nt; nt++)
        acc[nt][0] = acc[nt][1] = acc[nt][2] = acc[nt][3] = 0.f;
    const float* base = Aw + (16 * m + g) * RS + 2 * tig;
#pragma unroll
    for (int kt = 0; kt < Kt; kt++) {
        const float* ar = base + kt * 16;
        float2 va = *(const float2*)(ar);
        float2 vc = *(const float2*)(ar + 8 * RS);
        float2 vb = *(const float2*)(ar + 8);
        float2 vd = *(const float2*)(ar + 8 * RS + 8);
        uint32_t ah[4], al[4];
        ah[0] = pkb(va.x, va.y); al[0] = pkb(va.x - lof(ah[0]), va.y - hif(ah[0]));
        ah[1] = pkb(vc.x, vc.y); al[1] = pkb(vc.x - lof(ah[1]), vc.y - hif(ah[1]));
        ah[2] = pkb(vb.x, vb.y); al[2] = pkb(vb.x - lof(ah[2]), vb.y - hif(ah[2]));
        ah[3] = pkb(vd.x, vd.y); al[3] = pkb(vd.x - lof(ah[3]), vd.y - hif(ah[3]));
#pragma unroll
        for (int nt = 0; nt < Nt; nt++) {
            uint4 B = Wf[(nt * Kt + kt) * 32 + lane];
            mma16(acc[nt], ah, B.x, B.y);
            mma16(acc[nt], al, B.x, B.y);
            mma16(acc[nt], ah, B.z, B.w);
        }
    }
}

template<int K, int N>
__device__ __forceinline__ void layer_relu(const uint4* __restrict__ Wf,
                                           const float* __restrict__ bias,
                                           float* __restrict__ Aw, int lane)
{
    constexpr int Nt = N / 8;
    const int g = lane >> 2, tig = lane & 3;
#pragma unroll
    for (int m = 0; m < 2; m++) {
        float acc[Nt][4];
        mma_compute<K, N>(Wf, Aw, m, lane, acc);
        __syncwarp();
        float* s0 = Aw + (16 * m + g) * RS + 2 * tig;
#pragma unroll
        for (int nt = 0; nt < Nt; nt++) {
            float b0 = bias[nt * 8 + 2 * tig], b1 = bias[nt * 8 + 2 * tig + 1];
            *(float2*)(s0 + nt * 8) =
                make_float2(fmaxf(acc[nt][0] + b0, 0.f), fmaxf(acc[nt][1] + b1, 0.f));
            *(float2*)(s0 + 8 * RS + nt * 8) =
                make_float2(fmaxf(acc[nt][2] + b0, 0.f), fmaxf(acc[nt][3] + b1, 0.f));
        }
        // no sync: m1 reads rows 16..31, disjoint from m0's stores
    }
    __syncwarp();
}

// density layer 2: 64 -> 16, no relu, writes cols 16..31
__device__ __forceinline__ void layer_l2(const uint4* __restrict__ Wf,
                                         const float* __restrict__ bias,
                                         float* __restrict__ Aw, int lane)
{
    const int g = lane >> 2, tig = lane & 3;
#pragma unroll
    for (int m = 0; m < 2; m++) {
        float acc[2][4];
        mma_compute<64, 16>(Wf, Aw, m, lane, acc);
        __syncwarp();
        float* s0 = Aw + (16 * m + g) * RS + 16 + 2 * tig;
#pragma unroll
        for (int nt = 0; nt < 2; nt++) {
            float b0 = bias[nt * 8 + 2 * tig], b1 = bias[nt * 8 + 2 * tig + 1];
            *(float2*)(s0 + nt * 8) = make_float2(acc[nt][0] + b0, acc[nt][1] + b1);
            *(float2*)(s0 + 8 * RS + nt * 8) = make_float2(acc[nt][2] + b0, acc[nt][3] + b1);
        }
    }
    __syncwarp();
}

__device__ __forceinline__ float sigm(float v) {
    return __fdividef(1.f, 1.f + __expf(-v));
}

__device__ __forceinline__ void layer_c4(const uint4* __restrict__ Wf,
                                         const float* __restrict__ bias,
                                         const float* __restrict__ Aw, int lane,
                                         float* __restrict__ out, int pbase)
{
    const int g = lane >> 2, tig = lane & 3;
#pragma unroll
    for (int m = 0; m < 2; m++) {
        float acc[1][4];
        mma_compute<64, 8>(Wf, Aw, m, lane, acc);
        int r0 = pbase + 16 * m + g;
        int c = 2 * tig;
        if (c < 3) {
            float b = bias[c];
            out[NPTS + 3 * r0 + c]       = sigm(acc[0][0] + b);
            out[NPTS + 3 * (r0 + 8) + c] = sigm(acc[0][2] + b);
        }
        if (c + 1 < 3) {
            float b = bias[c + 1];
            out[NPTS + 3 * r0 + c + 1]       = sigm(acc[0][1] + b);
            out[NPTS + 3 * (r0 + 8) + c + 1] = sigm(acc[0][3] + b);
        }
    }
    __syncwarp();   // protect staging reads from next tile's feature stores
}

__device__ __forceinline__ void stage_w(uint4* __restrict__ dst, const float* __restrict__ w,
                                        int Kt, int Nt, int rN, int tid)
{
    int tot = Kt * Nt * 32;
    for (int idx = tid; idx < tot; idx += THREADS) {
        int lane = idx & 31, f = idx >> 5;
        int kt = f % Kt, nt = f / Kt;
        int g = lane >> 2, tig = lane & 3;
        int n = nt * 8 + g;
        int k0 = kt * 16 + 2 * tig;
        float w00 = 0.f, w01 = 0.f, w10 = 0.f, w11 = 0.f;
        if (n < rN) {
            w00 = w[k0 * rN + n];       w01 = w[(k0 + 1) * rN + n];
            w10 = w[(k0 + 8) * rN + n]; w11 = w[(k0 + 9) * rN + n];
        }
        uint32_t h0 = pkb(w00, w01), h1 = pkb(w10, w11);
        uint32_t l0 = pkb(w00 - lof(h0), w01 - hif(h0));
        uint32_t l1 = pkb(w10 - lof(h1), w11 - hif(h1));
        dst[idx] = make_uint4(h0, h1, l0, l1);
    }
}

__global__ void __launch_bounds__(THREADS, 1)
nerf_mma_kernel(const float* __restrict__ coords,
                const float* __restrict__ dirs,
                const u64*   __restrict__ emb,
                const float* __restrict__ dw1, const float* __restrict__ db1,
                const float* __restrict__ dw2, const float* __restrict__ db2,
                const float* __restrict__ cw1, const float* __restrict__ cb1,
                const float* __restrict__ cw2, const float* __restrict__ cb2,
                const float* __restrict__ cw3, const float* __restrict__ cb3,
                const float* __restrict__ cw4, const float* __restrict__ cb4,
                float* __restrict__ out)
{
    extern __shared__ float sm[];
    uint4* wf = (uint4*)sm;
    const int tid = threadIdx.x;

    stage_w(wf + WF_L1, dw1, 2, 8, 64, tid);
    stage_w(wf + WF_L2, dw2, 4, 2, 16, tid);
    stage_w(wf + WF_C1, cw1, 2, 8, 64, tid);
    stage_w(wf + WF_C2, cw2, 4, 8, 64, tid);
    stage_w(wf + WF_C3, cw3, 4, 8, 64, tid);
    stage_w(wf + WF_C4, cw4, 4, 1,  3, tid);
    for (int i = tid; i < 64; i += THREADS) sm[BIAS_F + i] = db1[i];
    for (int i = tid; i < 16; i += THREADS) sm[BIAS_F + 64 + i] = db2[i];
    for (int i = tid; i < 64; i += THREADS) sm[BIAS_F + 80 + i] = cb1[i];
    for (int i = tid; i < 64; i += THREADS) sm[BIAS_F + 144 + i] = cb2[i];
    for (int i = tid; i < 64; i += THREADS) sm[BIAS_F + 208 + i] = cb3[i];
    for (int i = tid; i < 8;  i += THREADS) sm[BIAS_F + 272 + i] = (i < 3) ? cb4[i] : 0.f;
    __syncthreads();

    const int lane = tid & 31, warp = tid >> 5;
    float* Aw = sm + STG_F + warp * (32 * RS);
    float* frow = Aw + lane * RS;

    const float RESV[16] = {16.f, 20.f, 25.f, 32.f, 40.f, 50.f, 64.f, 80.f,
                            101.f, 128.f, 161.f, 203.f, 256.f, 322.f, 406.f, 512.f};

    for (int wt = blockIdx.x * NWARP + warp; wt < NWTILES; wt += NCTA * NWARP) {
        const int p = wt * 32 + lane;

        // ---------- hash-grid encode (1 point per lane) ----------
        const float cx = coords[3 * p + 0];
        const float cy = coords[3 * p + 1];
        const float cz = coords[3 * p + 2];
        float dxr = dirs[3 * p + 0];
        float dyr = dirs[3 * p + 1];
        float dzr = dirs[3 * p + 2];

#pragma unroll
        for (int l = 0; l < 16; l++) {
            const float r = RESV[l];
            float fx = cx * r, fy = cy * r, fz = cz * r;
            float xf = floorf(fx), yf = floorf(fy), zf = floorf(fz);
            float tx = fx - xf, ty = fy - yf, tz = fz - zf;
            uint32_t px = (uint32_t)xf, py = (uint32_t)yf, pz = (uint32_t)zf;
            uint32_t hx0 = px,                hx1 = px + 1u;
            uint32_t hy0 = py * 2654435761u,  hy1 = hy0 + 2654435761u;
            uint32_t hz0 = pz * 805459861u,   hz1 = hz0 + 805459861u;
            const u64* tt = emb + ((size_t)l << 19);
            u64 e000 = __ldg(tt + ((hx0 ^ hy0 ^ hz0) & TMASK));
            u64 e001 = __ldg(tt + ((hx0 ^ hy0 ^ hz1) & TMASK));
            u64 e010 = __ldg(tt + ((hx0 ^ hy1 ^ hz0) & TMASK));
            u64 e011 = __ldg(tt + ((hx0 ^ hy1 ^ hz1) & TMASK));
            u64 e100 = __ldg(tt + ((hx1 ^ hy0 ^ hz0) & TMASK));
            u64 e101 = __ldg(tt + ((hx1 ^ hy0 ^ hz1) & TMASK));
            u64 e110 = __ldg(tt + ((hx1 ^ hy1 ^ hz0) & TMASK));
            u64 e111 = __ldg(tt + ((hx1 ^ hy1 ^ hz1) & TMASK));

            float ux = 1.f - tx, uy = 1.f - ty, uz = 1.f - tz;
            float w00 = ux * uy, w01 = ux * ty, w10 = tx * uy, w11 = tx * ty;
            float2 v; float a0 = 0.f, a1 = 0.f, w;
            w = w00 * uz; v = *(float2*)&e000; a0 = fmaf(w, v.x, a0); a1 = fmaf(w, v.y, a1);
            w = w00 * tz; v = *(float2*)&e001; a0 = fmaf(w, v.x, a0); a1 = fmaf(w, v.y, a1);
            w = w01 * uz; v = *(float2*)&e010; a0 = fmaf(w, v.x, a0); a1 = fmaf(w, v.y, a1);
            w = w01 * tz; v = *(float2*)&e011; a0 = fmaf(w, v.x, a0); a1 = fmaf(w, v.y, a1);
            w = w10 * uz; v = *(float2*)&e100; a0 = fmaf(w, v.x, a0); a1 = fmaf(w, v.y, a1);
            w = w10 * tz; v = *(float2*)&e101; a0 = fmaf(w, v.x, a0); a1 = fmaf(w, v.y, a1);
            w = w11 * uz; v = *(float2*)&e110; a0 = fmaf(w, v.x, a0); a1 = fmaf(w, v.y, a1);
            w = w11 * tz; v = *(float2*)&e111; a0 = fmaf(w, v.x, a0); a1 = fmaf(w, v.y, a1);
            *(float2*)(frow + 2 * l) = make_float2(a0, a1);
        }
        __syncwarp();

        // ---------- density MLP ----------
        layer_relu<32, 64>(wf + WF_L1, sm + BIAS_F, Aw, lane);
        layer_l2(wf + WF_L2, sm + BIAS_F + 64, Aw, lane);

        out[p] = __expf(frow[16]);

        // ---------- SH deg-4 into cols 0..15 ----------
        {
            float inv = rsqrtf(dxr * dxr + dyr * dyr + dzr * dzr);
            float x = dxr * inv, y = dyr * inv, z = dzr * inv;
            float xx = x * x, yy = y * y, zz = z * z;
            float xy = x * y, yz = y * z, xz = x * z;
            *(float4*)(frow + 0) = make_float4(
                0.28209479177387814f,
                -0.48860251190291987f * y,
                 0.48860251190291987f * z,
                -0.48860251190291987f * x);
            *(float4*)(frow + 4) = make_float4(
                 1.0925484305920792f * xy,
                -1.0925484305920792f * yz,
                 0.94617469575756f * zz - 0.31539156525252f,
                -1.0925484305920792f * xz);
            *(float4*)(frow + 8) = make_float4(
                 0.5462742152960396f * (xx - yy),
                 0.5900435899266435f * y * (-3.0f * xx + yy),
                 2.890611442640554f * xy * z,
                 0.4570457994644657f * y * (1.0f - 5.0f * zz));
            *(float4*)(frow + 12) = make_float4(
                 0.3731763325901154f * z * (5.0f * zz - 3.0f),
                 0.4570457994644657f * x * (1.0f - 5.0f * zz),
                 1.445305721320277f * z * (xx - yy),
                 0.5900435899266435f * x * (xx - 3.0f * yy));
        }
        __syncwarp();

        // ---------- color MLP ----------
        layer_relu<32, 64>(wf + WF_C1, sm + BIAS_F + 80,  Aw, lane);
        layer_relu<64, 64>(wf + WF_C2, sm + BIAS_F + 144, Aw, lane);
        layer_relu<64, 64>(wf + WF_C3, sm + BIAS_F + 208, Aw, lane);
        layer_c4(wf + WF_C4, sm + BIAS_F + 272, Aw, lane, out, wt * 32);
    }
}

extern "C" void kernel_launch(void* const* d_in, const int* in_sizes, int n_in,
                              void* d_out, int out_size)
{
    const float* coords = (const float*)d_in[0];
    const float* dirs   = (const float*)d_in[1];
    const u64*   emb    = (const u64*)d_in[2];
    const float* dw1 = (const float*)d_in[3];
    const float* db1 = (const float*)d_in[4];
    const float* dw2 = (const float*)d_in[5];
    const float* db2 = (const float*)d_in[6];
    const float* cw1 = (const float*)d_in[7];
    const float* cb1 = (const float*)d_in[8];
    const float* cw2 = (const float*)d_in[9];
    const float* cb2 = (const float*)d_in[10];
    const float* cw3 = (const float*)d_in[11];
    const float* cb3 = (const float*)d_in[12];
    const float* cw4 = (const float*)d_in[13];
    const float* cb4 = (const float*)d_in[14];
    float* out = (float*)d_out;

    cudaFuncSetAttribute(nerf_mma_kernel,
                         cudaFuncAttributeMaxDynamicSharedMemorySize, SMEM_BYTES);

    nerf_mma_kernel<<<NCTA, THREADS, SMEM_BYTES>>>(
        coords, dirs, emb,
        dw1, db1, dw2, db2,
        cw1, cb1, cw2, cb2, cw3, cb3, cw4, cb4,
        out);
}